// round 15
// baseline (speedup 1.0000x reference)
#include <cuda_runtime.h>
#include <cuda_bf16.h>
#include <math.h>
#include <stdint.h>

#define BATCH 4
#define IMH 64
#define IMW 64
#define CDIM 128
#define NPIX (BATCH * IMH * IMW)   // 16384
#define NHEADS 4
#define HD 32
#define NBK 7
#define HID 512

// Scratch (device globals — no allocation allowed)
__device__ __nv_bfloat16 g_xn[NPIX * CDIM];        // LN1 out
__device__ __nv_bfloat16 g_qkv[NPIX * 3 * CDIM];   // qkv bf16
__device__ __nv_bfloat16 g_attn[NPIX * CDIM];      // attn out
__device__ float g_h[NPIX * CDIM];                 // residual 1 (fp32)
__device__ __nv_bfloat16 g_y[NPIX * CDIM];         // LN2 out
__device__ __nv_bfloat16 g_mlp[NPIX * HID];        // fc1+gelu out
// bf16 transposed weights: BT[n][k] = W[k][n]
__device__ __nv_bfloat16 g_wqkvT[384 * 128];
__device__ __nv_bfloat16 g_wprojT[128 * 128];
__device__ __nv_bfloat16 g_wfc1T[512 * 128];
__device__ __nv_bfloat16 g_wfc2T[128 * 512];

// ---------------------------------------------------------------------------
// PTX helpers (compute_103-safe)
// ---------------------------------------------------------------------------
__device__ __forceinline__ uint32_t smem_u32(const void* p) {
    uint32_t a;
    asm("{ .reg .u64 t; cvta.to.shared.u64 t, %1; cvt.u32.u64 %0, t; }"
        : "=r"(a) : "l"(p));
    return a;
}
__device__ __forceinline__ void ldm_x4(uint32_t* r, uint32_t addr) {
    asm volatile("ldmatrix.sync.aligned.m8n8.x4.shared.b16 {%0,%1,%2,%3}, [%4];"
                 : "=r"(r[0]), "=r"(r[1]), "=r"(r[2]), "=r"(r[3]) : "r"(addr));
}
__device__ __forceinline__ void ldm_x2(uint32_t* r, uint32_t addr) {
    asm volatile("ldmatrix.sync.aligned.m8n8.x2.shared.b16 {%0,%1}, [%2];"
                 : "=r"(r[0]), "=r"(r[1]) : "r"(addr));
}
__device__ __forceinline__ void mma_bf16(float* c, const uint32_t* a,
                                         const uint32_t* b) {
    asm volatile(
        "mma.sync.aligned.m16n8k16.row.col.f32.bf16.bf16.f32 "
        "{%0,%1,%2,%3}, {%4,%5,%6,%7}, {%8,%9}, {%0,%1,%2,%3};"
        : "+f"(c[0]), "+f"(c[1]), "+f"(c[2]), "+f"(c[3])
        : "r"(a[0]), "r"(a[1]), "r"(a[2]), "r"(a[3]), "r"(b[0]), "r"(b[1]));
}
__device__ __forceinline__ void cp_async16(uint32_t dst, const void* src) {
    asm volatile("cp.async.cg.shared.global [%0], [%1], 16;"
                 :: "r"(dst), "l"(src));
}
#define CP_COMMIT() asm volatile("cp.async.commit_group;")
#define CP_WAIT(n)  asm volatile("cp.async.wait_group %0;" :: "n"(n))

__device__ __forceinline__ float2 bf2f(uint32_t u) {
    float lo = __uint_as_float(u << 16);
    float hi = __uint_as_float(u & 0xffff0000u);
    return make_float2(lo, hi);
}

// ---------------------------------------------------------------------------
// Fused LN1 + weight prep. Blocks [0, NPIX): LN rows (128 threads used as a
// full block). Blocks [NPIX, NPIX+1536): weight transpose, 128 items each.
// ---------------------------------------------------------------------------
__global__ void ln_prep_kernel(const float* __restrict__ x,
                               const float* __restrict__ gamma,
                               const float* __restrict__ beta,
                               __nv_bfloat16* __restrict__ out,
                               const float* __restrict__ qkv_w,
                               const float* __restrict__ proj_w,
                               const float* __restrict__ fc1_w,
                               const float* __restrict__ fc2_w) {
    if (blockIdx.x < NPIX) {
        int row = blockIdx.x;
        int t = threadIdx.x;
        float v = x[row * CDIM + t];

        __shared__ float s1[4], s2[4];
        int lane = t & 31, warp = t >> 5;

        float ws = v;
        #pragma unroll
        for (int off = 16; off; off >>= 1) ws += __shfl_xor_sync(0xffffffffu, ws, off);
        if (lane == 0) s1[warp] = ws;
        __syncthreads();
        float mean = (s1[0] + s1[1] + s1[2] + s1[3]) * (1.0f / CDIM);

        float d = v - mean;
        float ws2 = d * d;
        #pragma unroll
        for (int off = 16; off; off >>= 1) ws2 += __shfl_xor_sync(0xffffffffu, ws2, off);
        if (lane == 0) s2[warp] = ws2;
        __syncthreads();
        float var = (s2[0] + s2[1] + s2[2] + s2[3]) * (1.0f / CDIM);

        out[row * CDIM + t] =
            __float2bfloat16(d * rsqrtf(var + 1e-5f) * gamma[t] + beta[t]);
        return;
    }

    int t = (blockIdx.x - NPIX) * 128 + threadIdx.x;   // 0..196607
    if (t < 49152) {
        int n = t / 128, k = t % 128;
        g_wqkvT[t] = __float2bfloat16(qkv_w[k * 384 + n]);
        return;
    }
    t -= 49152;
    if (t < 16384) {
        int n = t / 128, k = t % 128;
        g_wprojT[t] = __float2bfloat16(proj_w[k * 128 + n]);
        return;
    }
    t -= 16384;
    if (t < 65536) {
        int n = t / 128, k = t % 128;
        g_wfc1T[t] = __float2bfloat16(fc1_w[k * 512 + n]);
        return;
    }
    t -= 65536;
    if (t < 65536) {
        int n = t / 512, k = t % 512;
        g_wfc2T[t] = __float2bfloat16(fc2_w[k * 128 + n]);
    }
}

// ---------------------------------------------------------------------------
// bf16 mma.sync GEMM + cp.async 2-stage pipeline (R11 64x128 config).
// epi: 0=bias, 1=bias+res, 2=bias+gelu.  obf: output bf16 (else fp32).
// ---------------------------------------------------------------------------
#define BMT 64
#define BNT 128
#define BKT 32
#define ASTR 40   // 40 bf16 = 80B row stride

__global__ void mma_gemm_kernel(const __nv_bfloat16* __restrict__ A,
                                const __nv_bfloat16* __restrict__ BT,
                                const float* __restrict__ bias,
                                const float* __restrict__ res,
                                void* __restrict__ Cv,
                                int N, int Kdim, int epi, int obf) {
    __shared__ __nv_bfloat16 As[2][BMT][ASTR];
    __shared__ __nv_bfloat16 Bs[2][BNT][ASTR];

    int tid = threadIdx.x;
    int wid = tid >> 5, lane = tid & 31;
    int warp_m = wid >> 2, warp_n = wid & 3;
    int m0 = blockIdx.y * BMT;
    int n0 = blockIdx.x * BNT;

    float acc[2][4][4] = {};

    int ldRow = tid >> 2, ldCh = tid & 3;
    const __nv_bfloat16* Ag  = A  + (long)(m0 + ldRow) * Kdim + ldCh * 8;
    const __nv_bfloat16* Bg0 = BT + (long)(n0 + ldRow) * Kdim + ldCh * 8;
    const __nv_bfloat16* Bg1 = BT + (long)(n0 + 64 + ldRow) * Kdim + ldCh * 8;
    uint32_t aDst = smem_u32(&As[0][ldRow][ldCh * 8]);
    uint32_t bDst0 = smem_u32(&Bs[0][ldRow][ldCh * 8]);
    uint32_t bDst1 = smem_u32(&Bs[0][64 + ldRow][ldCh * 8]);
    const uint32_t A_SS = BMT * ASTR * 2;
    const uint32_t B_SS = BNT * ASTR * 2;

    uint32_t aAddr[2], bAddr[4];
    #pragma unroll
    for (int mt = 0; mt < 2; mt++)
        aAddr[mt] = smem_u32(&As[0][warp_m * 32 + mt * 16 + (lane & 15)][(lane >> 4) * 8]);
    #pragma unroll
    for (int nt = 0; nt < 4; nt++)
        bAddr[nt] = smem_u32(&Bs[0][warp_n * 32 + nt * 8 + (lane & 7)][((lane >> 3) & 1) * 8]);

    int nc = Kdim >> 5;
    cp_async16(aDst, Ag);
    cp_async16(bDst0, Bg0);
    cp_async16(bDst1, Bg1);
    CP_COMMIT();

    for (int c = 0; c < nc; c++) {
        if (c + 1 < nc) {
            int kc = (c + 1) << 5;
            uint32_t s = ((c + 1) & 1);
            cp_async16(aDst + s * A_SS, Ag + kc);
            cp_async16(bDst0 + s * B_SS, Bg0 + kc);
            cp_async16(bDst1 + s * B_SS, Bg1 + kc);
            CP_COMMIT();
            CP_WAIT(1);
        } else {
            CP_WAIT(0);
        }
        __syncthreads();

        uint32_t sa = (c & 1) * A_SS, sb = (c & 1) * B_SS;
        #pragma unroll
        for (int ks = 0; ks < 2; ks++) {
            uint32_t af[2][4], bf[4][2];
            #pragma unroll
            for (int mt = 0; mt < 2; mt++)
                ldm_x4(af[mt], aAddr[mt] + sa + ks * 32);
            #pragma unroll
            for (int nt = 0; nt < 4; nt++)
                ldm_x2(bf[nt], bAddr[nt] + sb + ks * 32);
            #pragma unroll
            for (int mt = 0; mt < 2; mt++)
                #pragma unroll
                for (int nt = 0; nt < 4; nt++)
                    mma_bf16(acc[mt][nt], af[mt], bf[nt]);
        }
        __syncthreads();
    }

    int trow = lane >> 2, tcol = (lane & 3) * 2;
    #pragma unroll
    for (int mt = 0; mt < 2; mt++) {
        #pragma unroll
        for (int nt = 0; nt < 4; nt++) {
            int col = n0 + warp_n * 32 + nt * 8 + tcol;
            float b0 = bias[col], b1 = bias[col + 1];
            #pragma unroll
            for (int hh = 0; hh < 2; hh++) {
                int row = m0 + warp_m * 32 + mt * 16 + trow + hh * 8;
                float v0 = acc[mt][nt][hh * 2 + 0] + b0;
                float v1 = acc[mt][nt][hh * 2 + 1] + b1;
                if (epi == 1) {
                    float2 rv = *reinterpret_cast<const float2*>(
                        &res[(long)row * N + col]);
                    v0 += rv.x; v1 += rv.y;
                } else if (epi == 2) {
                    v0 = 0.5f * v0 * (1.0f + erff(v0 * 0.7071067811865476f));
                    v1 = 0.5f * v1 * (1.0f + erff(v1 * 0.7071067811865476f));
                }
                if (obf) {
                    __nv_bfloat162 p = __float22bfloat162_rn(make_float2(v0, v1));
                    *reinterpret_cast<uint32_t*>(
                        (__nv_bfloat16*)Cv + (long)row * N + col) =
                        *reinterpret_cast<uint32_t*>(&p);
                } else {
                    float2 ov = {v0, v1};
                    *reinterpret_cast<float2*>(
                        (float*)Cv + (long)row * N + col) = ov;
                }
            }
        }
    }
}

// ---------------------------------------------------------------------------
// Proj GEMM + residual + fused LN2 (64x128 tiles, R11 config).
// ---------------------------------------------------------------------------
__global__ void proj_ln_kernel(const __nv_bfloat16* __restrict__ A,
                               const __nv_bfloat16* __restrict__ BT,
                               const float* __restrict__ bias,
                               const float* __restrict__ res,
                               const float* __restrict__ g2,
                               const float* __restrict__ b2,
                               float* __restrict__ H,
                               __nv_bfloat16* __restrict__ Y) {
    const int N = 128, Kdim = 128;
    __shared__ __nv_bfloat16 As[2][BMT][ASTR];
    __shared__ __nv_bfloat16 Bs[2][BNT][ASTR];
    __shared__ float rsum[4][64], rsq[4][64];
    __shared__ float smean[64], srstd[64];

    int tid = threadIdx.x;
    int wid = tid >> 5, lane = tid & 31;
    int warp_m = wid >> 2, warp_n = wid & 3;
    int m0 = blockIdx.y * BMT;

    float acc[2][4][4] = {};

    int ldRow = tid >> 2, ldCh = tid & 3;
    const __nv_bfloat16* Ag  = A  + (long)(m0 + ldRow) * Kdim + ldCh * 8;
    const __nv_bfloat16* Bg0 = BT + (long)ldRow * Kdim + ldCh * 8;
    const __nv_bfloat16* Bg1 = BT + (long)(64 + ldRow) * Kdim + ldCh * 8;
    uint32_t aDst = smem_u32(&As[0][ldRow][ldCh * 8]);
    uint32_t bDst0 = smem_u32(&Bs[0][ldRow][ldCh * 8]);
    uint32_t bDst1 = smem_u32(&Bs[0][64 + ldRow][ldCh * 8]);
    const uint32_t A_SS = BMT * ASTR * 2;
    const uint32_t B_SS = BNT * ASTR * 2;

    uint32_t aAddr[2], bAddr[4];
    #pragma unroll
    for (int mt = 0; mt < 2; mt++)
        aAddr[mt] = smem_u32(&As[0][warp_m * 32 + mt * 16 + (lane & 15)][(lane >> 4) * 8]);
    #pragma unroll
    for (int nt = 0; nt < 4; nt++)
        bAddr[nt] = smem_u32(&Bs[0][warp_n * 32 + nt * 8 + (lane & 7)][((lane >> 3) & 1) * 8]);

    cp_async16(aDst, Ag);
    cp_async16(bDst0, Bg0);
    cp_async16(bDst1, Bg1);
    CP_COMMIT();

    for (int c = 0; c < 4; c++) {
        if (c < 3) {
            int kc = (c + 1) << 5;
            uint32_t s = ((c + 1) & 1);
            cp_async16(aDst + s * A_SS, Ag + kc);
            cp_async16(bDst0 + s * B_SS, Bg0 + kc);
            cp_async16(bDst1 + s * B_SS, Bg1 + kc);
            CP_COMMIT();
            CP_WAIT(1);
        } else {
            CP_WAIT(0);
        }
        __syncthreads();

        uint32_t sa = (c & 1) * A_SS, sb = (c & 1) * B_SS;
        #pragma unroll
        for (int ks = 0; ks < 2; ks++) {
            uint32_t af[2][4], bf[4][2];
            #pragma unroll
            for (int mt = 0; mt < 2; mt++)
                ldm_x4(af[mt], aAddr[mt] + sa + ks * 32);
            #pragma unroll
            for (int nt = 0; nt < 4; nt++)
                ldm_x2(bf[nt], bAddr[nt] + sb + ks * 32);
            #pragma unroll
            for (int mt = 0; mt < 2; mt++)
                #pragma unroll
                for (int nt = 0; nt < 4; nt++)
                    mma_bf16(acc[mt][nt], af[mt], bf[nt]);
        }
        __syncthreads();
    }

    int trow = lane >> 2, tcol = (lane & 3) * 2;
    float vals[2][4][2][2];
    #pragma unroll
    for (int mt = 0; mt < 2; mt++) {
        #pragma unroll
        for (int nt = 0; nt < 4; nt++) {
            int col = warp_n * 32 + nt * 8 + tcol;
            float b0 = bias[col], b1 = bias[col + 1];
            #pragma unroll
            for (int hh = 0; hh < 2; hh++) {
                int row = m0 + warp_m * 32 + mt * 16 + trow + hh * 8;
                float2 rv = *reinterpret_cast<const float2*>(&res[(long)row * N + col]);
                vals[mt][nt][hh][0] = acc[mt][nt][hh * 2 + 0] + b0 + rv.x;
                vals[mt][nt][hh][1] = acc[mt][nt][hh * 2 + 1] + b1 + rv.y;
            }
        }
    }
    #pragma unroll
    for (int mt = 0; mt < 2; mt++) {
        #pragma unroll
        for (int hh = 0; hh < 2; hh++) {
            float s = 0.0f, sq = 0.0f;
            #pragma unroll
            for (int nt = 0; nt < 4; nt++) {
                float a = vals[mt][nt][hh][0], bb = vals[mt][nt][hh][1];
                s += a + bb;
                sq += a * a + bb * bb;
            }
            s  += __shfl_xor_sync(0xffffffffu, s, 1);
            s  += __shfl_xor_sync(0xffffffffu, s, 2);
            sq += __shfl_xor_sync(0xffffffffu, sq, 1);
            sq += __shfl_xor_sync(0xffffffffu, sq, 2);
            if ((lane & 3) == 0) {
                int lr = warp_m * 32 + mt * 16 + trow + hh * 8;
                rsum[warp_n][lr] = s;
                rsq[warp_n][lr] = sq;
            }
        }
    }
    __syncthreads();
    if (tid < 64) {
        float su = rsum[0][tid] + rsum[1][tid] + rsum[2][tid] + rsum[3][tid];
        float sq = rsq[0][tid] + rsq[1][tid] + rsq[2][tid] + rsq[3][tid];
        float mean = su * (1.0f / 128.0f);
        float var = sq * (1.0f / 128.0f) - mean * mean;
        smean[tid] = mean;
        srstd[tid] = rsqrtf(var + 1e-5f);
    }
    __syncthreads();

    #pragma unroll
    for (int mt = 0; mt < 2; mt++) {
        #pragma unroll
        for (int nt = 0; nt < 4; nt++) {
            int col = warp_n * 32 + nt * 8 + tcol;
            float gg0 = g2[col], gg1 = g2[col + 1];
            float bb0 = b2[col], bb1 = b2[col + 1];
            #pragma unroll
            for (int hh = 0; hh < 2; hh++) {
                int lr = warp_m * 32 + mt * 16 + trow + hh * 8;
                int row = m0 + lr;
                float v0 = vals[mt][nt][hh][0], v1 = vals[mt][nt][hh][1];
                float2 hv = {v0, v1};
                *reinterpret_cast<float2*>(&H[(long)row * N + col]) = hv;
                float m = smean[lr], r = srstd[lr];
                float y0 = (v0 - m) * r * gg0 + bb0;
                float y1 = (v1 - m) * r * gg1 + bb1;
                __nv_bfloat162 p = __float22bfloat162_rn(make_float2(y0, y1));
                *reinterpret_cast<uint32_t*>(Y + (long)row * N + col) =
                    *reinterpret_cast<uint32_t*>(&p);
            }
        }
    }
}

// ---------------------------------------------------------------------------
// Fully fused neighborhood attention (R11 config, softmax without max-shift).
// Block = (by, h). 256 threads (8 warps).
// ---------------------------------------------------------------------------
__global__ void natt_kernel(const __nv_bfloat16* __restrict__ qkv,
                            const float* __restrict__ rpb,
                            __nv_bfloat16* __restrict__ out) {
    __shared__ uint32_t Vs[NBK * 64 * 16];      // 28672 B
    __shared__ float s_sc[NBK * 64];            // 1792 B
    __shared__ float rpb_s[169];                // 676 B
    __shared__ float wbuf[8][8][49];            // 12544 B
    __shared__ float qpart[8][HD];              // 1024 B
    __shared__ float qs[HD];                    // 128 B

    int blk = blockIdx.x;
    int by = blk >> 2, h = blk & 3;
    int b = by >> 6, y = by & 63;
    int sy = min(max(y - 3, 0), IMH - NBK);
    int tid = threadIdx.x;
    int wid = tid >> 5, lane = tid & 31;

    // --- qsum partial
    {
        int x = tid >> 2, dg = tid & 3;
        uint4 u = *reinterpret_cast<const uint4*>(
            &qkv[((long)(by * 64 + x)) * 384 + h * HD + dg * 8]);
        float2 f0 = bf2f(u.x), f1 = bf2f(u.y), f2 = bf2f(u.z), f3 = bf2f(u.w);
        float v[8] = {f0.x, f0.y, f1.x, f1.y, f2.x, f2.y, f3.x, f3.y};
        #pragma unroll
        for (int i = 0; i < 8; i++) {
            v[i] += __shfl_xor_sync(0xffffffffu, v[i], 4);
            v[i] += __shfl_xor_sync(0xffffffffu, v[i], 8);
            v[i] += __shfl_xor_sync(0xffffffffu, v[i], 16);
        }
        if (lane < 4) {
            #pragma unroll
            for (int i = 0; i < 8; i++)
                qpart[wid][lane * 8 + i] = v[i];
        }
    }

    // --- Stage V
    for (int i = tid; i < NBK * 64 * 4; i += 256) {
        int ky = i >> 8;
        int rem = i & 255;
        int col = rem >> 2, d8 = rem & 3;
        int np = (b * 64 + sy + ky) * 64 + col;
        uint4 u = *reinterpret_cast<const uint4*>(
            &qkv[(long)np * 384 + 2 * CDIM + h * HD + d8 * 8]);
        *reinterpret_cast<uint4*>(&Vs[((ky * 64 + col) << 4) + d8 * 4]) = u;
    }
    if (tid < 169) rpb_s[tid] = rpb[h * 169 + tid];
    __syncthreads();

    if (tid < HD) {
        float s = 0.0f;
        #pragma unroll
        for (int w = 0; w < 8; w++) s += qpart[w][tid];
        qs[tid] = s * 0.17677669529663687f;
    }
    __syncthreads();

    // --- Score dots: 448 dots, <=2 per thread
    #pragma unroll
    for (int rep = 0; rep < 2; rep++) {
        int d = rep * 256 + tid;
        if (d < NBK * 64) {
            int ky = d >> 6, nx = d & 63;
            const __nv_bfloat16* kb =
                qkv + ((long)((b * 64 + sy + ky) * 64 + nx)) * 384 + CDIM + h * HD;
            float acc = 0.0f;
            #pragma unroll
            for (int j = 0; j < 4; j++) {
                uint4 u = *reinterpret_cast<const uint4*>(kb + j * 8);
                float2 f0 = bf2f(u.x), f1 = bf2f(u.y), f2 = bf2f(u.z), f3 = bf2f(u.w);
                acc += f0.x * qs[j * 8 + 0] + f0.y * qs[j * 8 + 1]
                     + f1.x * qs[j * 8 + 2] + f1.y * qs[j * 8 + 3]
                     + f2.x * qs[j * 8 + 4] + f2.y * qs[j * 8 + 5]
                     + f3.x * qs[j * 8 + 6] + f3.y * qs[j * 8 + 7];
            }
            s_sc[d] = acc;
        }
    }
    __syncthreads();

    // --- Phase A: softmax weights (no max-shift: logits are O(±5))
    #pragma unroll 2
    for (int i = 0; i < 8; i++) {
        int x = wid * 8 + i;
        int sx = min(max(x - 3, 0), IMW - NBK);
        int ryo = (sy - y + 6) * 13 + (sx - x + 6);

        float e0, e1 = 0.0f;
        {
            int ky = lane / NBK, kx = lane - ky * NBK;
            e0 = __expf(s_sc[ky * 64 + sx + kx] + rpb_s[ryo + ky * 13 + kx]);
        }
        if (lane < 17) {
            int n = lane + 32;
            int ky = n / NBK, kx = n - ky * NBK;
            e1 = __expf(s_sc[ky * 64 + sx + kx] + rpb_s[ryo + ky * 13 + kx]);
        }
        float sum = e0 + e1;
        #pragma unroll
        for (int off = 16; off; off >>= 1)
            sum += __shfl_xor_sync(0xffffffffu, sum, off);
        float inv = 1.0f / sum;
        wbuf[wid][i][lane] = e0 * inv;
        if (lane < 17) wbuf[wid][i][lane + 32] = e1 * inv;
    }
    __syncwarp();

    // --- Phase B: lane = (g = lane>>2 pixel, qi = lane&3 quarter of channels)
    int g = lane >> 2, qi = lane & 3;
    int x = wid * 8 + g;
    int sx = min(max(x - 3, 0), IMW - NBK);
    const float* wp = wbuf[wid][g];

    float a0 = 0.f, a1 = 0.f, a2 = 0.f, a3 = 0.f,
          a4 = 0.f, a5 = 0.f, a6 = 0.f, a7 = 0.f;
    #pragma unroll
    for (int n = 0; n < 49; n++) {
        int ky = n / NBK, kx = n - ky * NBK;
        float wv = wp[n];
        uint4 u = *reinterpret_cast<const uint4*>(
            &Vs[((ky * 64 + sx + kx) << 4) + qi * 4]);
        float2 f0 = bf2f(u.x), f1 = bf2f(u.y), f2 = bf2f(u.z), f3 = bf2f(u.w);
        a0 = fmaf(wv, f0.x, a0); a1 = fmaf(wv, f0.y, a1);
        a2 = fmaf(wv, f1.x, a2); a3 = fmaf(wv, f1.y, a3);
        a4 = fmaf(wv, f2.x, a4); a5 = fmaf(wv, f2.y, a5);
        a6 = fmaf(wv, f3.x, a6); a7 = fmaf(wv, f3.y, a7);
    }
    int p = (b * 64 + y) * 64 + x;
    __nv_bfloat162 p0 = __float22bfloat162_rn(make_float2(a0, a1));
    __nv_bfloat162 p1 = __float22bfloat162_rn(make_float2(a2, a3));
    __nv_bfloat162 p2 = __float22bfloat162_rn(make_float2(a4, a5));
    __nv_bfloat162 p3 = __float22bfloat162_rn(make_float2(a6, a7));
    uint4 ov;
    ov.x = *reinterpret_cast<uint32_t*>(&p0);
    ov.y = *reinterpret_cast<uint32_t*>(&p1);
    ov.z = *reinterpret_cast<uint32_t*>(&p2);
    ov.w = *reinterpret_cast<uint32_t*>(&p3);
    *reinterpret_cast<uint4*>(out + (long)p * CDIM + h * HD + qi * 8) = ov;
}

// ---------------------------------------------------------------------------
extern "C" void kernel_launch(void* const* d_in, const int* in_sizes, int n_in,
                              void* d_out, int out_size) {
    const float* x      = (const float*)d_in[0];
    const float* ln1_g  = (const float*)d_in[1];
    const float* ln1_b  = (const float*)d_in[2];
    const float* qkv_w  = (const float*)d_in[3];
    const float* qkv_b  = (const float*)d_in[4];
    const float* rpb    = (const float*)d_in[5];
    const float* proj_w = (const float*)d_in[6];
    const float* proj_b = (const float*)d_in[7];
    const float* ln2_g  = (const float*)d_in[8];
    const float* ln2_b  = (const float*)d_in[9];
    const float* fc1_w  = (const float*)d_in[10];
    const float* fc1_b  = (const float*)d_in[11];
    const float* fc2_w  = (const float*)d_in[12];
    const float* fc2_b  = (const float*)d_in[13];
    float* out = (float*)d_out;

    __nv_bfloat16 *xn, *qkvb, *attnb, *yb, *mlpb;
    float *hb;
    cudaGetSymbolAddress((void**)&xn,    g_xn);
    cudaGetSymbolAddress((void**)&qkvb,  g_qkv);
    cudaGetSymbolAddress((void**)&attnb, g_attn);
    cudaGetSymbolAddress((void**)&hb,    g_h);
    cudaGetSymbolAddress((void**)&yb,    g_y);
    cudaGetSymbolAddress((void**)&mlpb,  g_mlp);
    __nv_bfloat16 *wqkvT, *wprojT, *wfc1T, *wfc2T;
    cudaGetSymbolAddress((void**)&wqkvT, g_wqkvT);
    cudaGetSymbolAddress((void**)&wprojT, g_wprojT);
    cudaGetSymbolAddress((void**)&wfc1T, g_wfc1T);
    cudaGetSymbolAddress((void**)&wfc2T, g_wfc2T);

    // 1. Fused LN1 + weight prep
    ln_prep_kernel<<<NPIX + 1536, 128>>>(x, ln1_g, ln1_b, xn,
                                         qkv_w, proj_w, fc1_w, fc2_w);
    // 2. QKV GEMM -> bf16 qkv
    mma_gemm_kernel<<<dim3(3, 256), 256>>>(xn, wqkvT, qkv_b, nullptr,
                                           qkvb, 384, 128, 0, 1);
    // 3. Fused neighborhood attention
    natt_kernel<<<BATCH * IMH * NHEADS, 256>>>(qkvb, rpb, attnb);
    // 4. Proj GEMM + residual(x) + LN2 -> h (fp32) & y (bf16)
    proj_ln_kernel<<<dim3(1, 256), 256>>>(attnb, wprojT, proj_b, x,
                                          ln2_g, ln2_b, hb, yb);
    // 5. FC1 GEMM + GELU (bf16 out)
    mma_gemm_kernel<<<dim3(4, 256), 256>>>(yb, wfc1T, fc1_b, nullptr,
                                           mlpb, 512, 128, 2, 1);
    // 6. FC2 GEMM + residual(h) -> out (fp32)
    mma_gemm_kernel<<<dim3(1, 256), 256>>>(mlpb, wfc2T, fc2_b, hb,
                                           out, 128, 512, 1, 0);
}

// round 16
// speedup vs baseline: 1.4457x; 1.4457x over previous
#include <cuda_runtime.h>
#include <cuda_bf16.h>
#include <math.h>
#include <stdint.h>

#define BATCH 4
#define IMH 64
#define IMW 64
#define CDIM 128
#define NPIX (BATCH * IMH * IMW)   // 16384
#define NHEADS 4
#define HD 32
#define NBK 7
#define HID 512

// Scratch (device globals — no allocation allowed)
__device__ __nv_bfloat16 g_xn[NPIX * CDIM];        // LN1 out
__device__ __nv_bfloat16 g_qkv[NPIX * 3 * CDIM];   // qkv bf16
__device__ __nv_bfloat16 g_attn[NPIX * CDIM];      // attn out
__device__ float g_h[NPIX * CDIM];                 // residual 1 (fp32)
__device__ __nv_bfloat16 g_y[NPIX * CDIM];         // LN2 out
__device__ __nv_bfloat16 g_mlp[NPIX * HID];        // fc1+gelu out
// bf16 transposed weights: BT[n][k] = W[k][n]
__device__ __nv_bfloat16 g_wqkvT[384 * 128];
__device__ __nv_bfloat16 g_wprojT[128 * 128];
__device__ __nv_bfloat16 g_wfc1T[512 * 128];
__device__ __nv_bfloat16 g_wfc2T[128 * 512];

// ---------------------------------------------------------------------------
// PTX helpers (compute_103-safe)
// ---------------------------------------------------------------------------
__device__ __forceinline__ uint32_t smem_u32(const void* p) {
    uint32_t a;
    asm("{ .reg .u64 t; cvta.to.shared.u64 t, %1; cvt.u32.u64 %0, t; }"
        : "=r"(a) : "l"(p));
    return a;
}
__device__ __forceinline__ void ldm_x4(uint32_t* r, uint32_t addr) {
    asm volatile("ldmatrix.sync.aligned.m8n8.x4.shared.b16 {%0,%1,%2,%3}, [%4];"
                 : "=r"(r[0]), "=r"(r[1]), "=r"(r[2]), "=r"(r[3]) : "r"(addr));
}
__device__ __forceinline__ void ldm_x2(uint32_t* r, uint32_t addr) {
    asm volatile("ldmatrix.sync.aligned.m8n8.x2.shared.b16 {%0,%1}, [%2];"
                 : "=r"(r[0]), "=r"(r[1]) : "r"(addr));
}
__device__ __forceinline__ void mma_bf16(float* c, const uint32_t* a,
                                         const uint32_t* b) {
    asm volatile(
        "mma.sync.aligned.m16n8k16.row.col.f32.bf16.bf16.f32 "
        "{%0,%1,%2,%3}, {%4,%5,%6,%7}, {%8,%9}, {%0,%1,%2,%3};"
        : "+f"(c[0]), "+f"(c[1]), "+f"(c[2]), "+f"(c[3])
        : "r"(a[0]), "r"(a[1]), "r"(a[2]), "r"(a[3]), "r"(b[0]), "r"(b[1]));
}
__device__ __forceinline__ void cp_async16(uint32_t dst, const void* src) {
    asm volatile("cp.async.cg.shared.global [%0], [%1], 16;"
                 :: "r"(dst), "l"(src));
}
#define CP_COMMIT() asm volatile("cp.async.commit_group;")
#define CP_WAIT(n)  asm volatile("cp.async.wait_group %0;" :: "n"(n))

__device__ __forceinline__ float2 bf2f(uint32_t u) {
    float lo = __uint_as_float(u << 16);
    float hi = __uint_as_float(u & 0xffff0000u);
    return make_float2(lo, hi);
}

// ---------------------------------------------------------------------------
// Weight prep: transpose + convert to bf16
// ---------------------------------------------------------------------------
__global__ void prep_w_kernel(const float* __restrict__ qkv_w,
                              const float* __restrict__ proj_w,
                              const float* __restrict__ fc1_w,
                              const float* __restrict__ fc2_w) {
    int t = blockIdx.x * blockDim.x + threadIdx.x;
    if (t < 49152) {
        int n = t / 128, k = t % 128;
        g_wqkvT[t] = __float2bfloat16(qkv_w[k * 384 + n]);
        return;
    }
    t -= 49152;
    if (t < 16384) {
        int n = t / 128, k = t % 128;
        g_wprojT[t] = __float2bfloat16(proj_w[k * 128 + n]);
        return;
    }
    t -= 16384;
    if (t < 65536) {
        int n = t / 128, k = t % 128;
        g_wfc1T[t] = __float2bfloat16(fc1_w[k * 512 + n]);
        return;
    }
    t -= 65536;
    if (t < 65536) {
        int n = t / 512, k = t % 512;
        g_wfc2T[t] = __float2bfloat16(fc2_w[k * 128 + n]);
    }
}

// ---------------------------------------------------------------------------
// bf16 mma.sync GEMM + cp.async 2-stage pipeline (R11 64x128 config),
// with __launch_bounds__(256,4) to lift occupancy 3->4 CTAs/SM.
// epi: 0=bias, 1=bias+res, 2=bias+gelu.  obf: output bf16 (else fp32).
// ---------------------------------------------------------------------------
#define BMT 64
#define BNT 128
#define BKT 32
#define ASTR 40   // 40 bf16 = 80B row stride

__global__ void __launch_bounds__(256, 4)
mma_gemm_kernel(const __nv_bfloat16* __restrict__ A,
                const __nv_bfloat16* __restrict__ BT,
                const float* __restrict__ bias,
                const float* __restrict__ res,
                void* __restrict__ Cv,
                int N, int Kdim, int epi, int obf) {
    __shared__ __nv_bfloat16 As[2][BMT][ASTR];
    __shared__ __nv_bfloat16 Bs[2][BNT][ASTR];

    int tid = threadIdx.x;
    int wid = tid >> 5, lane = tid & 31;
    int warp_m = wid >> 2, warp_n = wid & 3;
    int m0 = blockIdx.y * BMT;
    int n0 = blockIdx.x * BNT;

    float acc[2][4][4] = {};

    int ldRow = tid >> 2, ldCh = tid & 3;
    const __nv_bfloat16* Ag  = A  + (long)(m0 + ldRow) * Kdim + ldCh * 8;
    const __nv_bfloat16* Bg0 = BT + (long)(n0 + ldRow) * Kdim + ldCh * 8;
    const __nv_bfloat16* Bg1 = BT + (long)(n0 + 64 + ldRow) * Kdim + ldCh * 8;
    uint32_t aDst = smem_u32(&As[0][ldRow][ldCh * 8]);
    uint32_t bDst0 = smem_u32(&Bs[0][ldRow][ldCh * 8]);
    uint32_t bDst1 = smem_u32(&Bs[0][64 + ldRow][ldCh * 8]);
    const uint32_t A_SS = BMT * ASTR * 2;
    const uint32_t B_SS = BNT * ASTR * 2;

    uint32_t aAddr[2], bAddr[4];
    #pragma unroll
    for (int mt = 0; mt < 2; mt++)
        aAddr[mt] = smem_u32(&As[0][warp_m * 32 + mt * 16 + (lane & 15)][(lane >> 4) * 8]);
    #pragma unroll
    for (int nt = 0; nt < 4; nt++)
        bAddr[nt] = smem_u32(&Bs[0][warp_n * 32 + nt * 8 + (lane & 7)][((lane >> 3) & 1) * 8]);

    int nc = Kdim >> 5;
    cp_async16(aDst, Ag);
    cp_async16(bDst0, Bg0);
    cp_async16(bDst1, Bg1);
    CP_COMMIT();

    for (int c = 0; c < nc; c++) {
        if (c + 1 < nc) {
            int kc = (c + 1) << 5;
            uint32_t s = ((c + 1) & 1);
            cp_async16(aDst + s * A_SS, Ag + kc);
            cp_async16(bDst0 + s * B_SS, Bg0 + kc);
            cp_async16(bDst1 + s * B_SS, Bg1 + kc);
            CP_COMMIT();
            CP_WAIT(1);
        } else {
            CP_WAIT(0);
        }
        __syncthreads();

        uint32_t sa = (c & 1) * A_SS, sb = (c & 1) * B_SS;
        #pragma unroll
        for (int ks = 0; ks < 2; ks++) {
            uint32_t af[2][4], bf[4][2];
            #pragma unroll
            for (int mt = 0; mt < 2; mt++)
                ldm_x4(af[mt], aAddr[mt] + sa + ks * 32);
            #pragma unroll
            for (int nt = 0; nt < 4; nt++)
                ldm_x2(bf[nt], bAddr[nt] + sb + ks * 32);
            #pragma unroll
            for (int mt = 0; mt < 2; mt++)
                #pragma unroll
                for (int nt = 0; nt < 4; nt++)
                    mma_bf16(acc[mt][nt], af[mt], bf[nt]);
        }
        __syncthreads();
    }

    int trow = lane >> 2, tcol = (lane & 3) * 2;
    #pragma unroll
    for (int mt = 0; mt < 2; mt++) {
        #pragma unroll
        for (int nt = 0; nt < 4; nt++) {
            int col = n0 + warp_n * 32 + nt * 8 + tcol;
            float b0 = bias[col], b1 = bias[col + 1];
            #pragma unroll
            for (int hh = 0; hh < 2; hh++) {
                int row = m0 + warp_m * 32 + mt * 16 + trow + hh * 8;
                float v0 = acc[mt][nt][hh * 2 + 0] + b0;
                float v1 = acc[mt][nt][hh * 2 + 1] + b1;
                if (epi == 1) {
                    float2 rv = *reinterpret_cast<const float2*>(
                        &res[(long)row * N + col]);
                    v0 += rv.x; v1 += rv.y;
                } else if (epi == 2) {
                    v0 = 0.5f * v0 * (1.0f + erff(v0 * 0.7071067811865476f));
                    v1 = 0.5f * v1 * (1.0f + erff(v1 * 0.7071067811865476f));
                }
                if (obf) {
                    __nv_bfloat162 p = __float22bfloat162_rn(make_float2(v0, v1));
                    *reinterpret_cast<uint32_t*>(
                        (__nv_bfloat16*)Cv + (long)row * N + col) =
                        *reinterpret_cast<uint32_t*>(&p);
                } else {
                    float2 ov = {v0, v1};
                    *reinterpret_cast<float2*>(
                        (float*)Cv + (long)row * N + col) = ov;
                }
            }
        }
    }
}

// ---------------------------------------------------------------------------
// Proj GEMM + residual + fused LN2 (64x128 tiles, R11 config).
// ---------------------------------------------------------------------------
__global__ void proj_ln_kernel(const __nv_bfloat16* __restrict__ A,
                               const __nv_bfloat16* __restrict__ BT,
                               const float* __restrict__ bias,
                               const float* __restrict__ res,
                               const float* __restrict__ g2,
                               const float* __restrict__ b2,
                               float* __restrict__ H,
                               __nv_bfloat16* __restrict__ Y) {
    const int N = 128, Kdim = 128;
    __shared__ __nv_bfloat16 As[2][BMT][ASTR];
    __shared__ __nv_bfloat16 Bs[2][BNT][ASTR];
    __shared__ float rsum[4][64], rsq[4][64];
    __shared__ float smean[64], srstd[64];

    int tid = threadIdx.x;
    int wid = tid >> 5, lane = tid & 31;
    int warp_m = wid >> 2, warp_n = wid & 3;
    int m0 = blockIdx.y * BMT;

    float acc[2][4][4] = {};

    int ldRow = tid >> 2, ldCh = tid & 3;
    const __nv_bfloat16* Ag  = A  + (long)(m0 + ldRow) * Kdim + ldCh * 8;
    const __nv_bfloat16* Bg0 = BT + (long)ldRow * Kdim + ldCh * 8;
    const __nv_bfloat16* Bg1 = BT + (long)(64 + ldRow) * Kdim + ldCh * 8;
    uint32_t aDst = smem_u32(&As[0][ldRow][ldCh * 8]);
    uint32_t bDst0 = smem_u32(&Bs[0][ldRow][ldCh * 8]);
    uint32_t bDst1 = smem_u32(&Bs[0][64 + ldRow][ldCh * 8]);
    const uint32_t A_SS = BMT * ASTR * 2;
    const uint32_t B_SS = BNT * ASTR * 2;

    uint32_t aAddr[2], bAddr[4];
    #pragma unroll
    for (int mt = 0; mt < 2; mt++)
        aAddr[mt] = smem_u32(&As[0][warp_m * 32 + mt * 16 + (lane & 15)][(lane >> 4) * 8]);
    #pragma unroll
    for (int nt = 0; nt < 4; nt++)
        bAddr[nt] = smem_u32(&Bs[0][warp_n * 32 + nt * 8 + (lane & 7)][((lane >> 3) & 1) * 8]);

    cp_async16(aDst, Ag);
    cp_async16(bDst0, Bg0);
    cp_async16(bDst1, Bg1);
    CP_COMMIT();

    for (int c = 0; c < 4; c++) {
        if (c < 3) {
            int kc = (c + 1) << 5;
            uint32_t s = ((c + 1) & 1);
            cp_async16(aDst + s * A_SS, Ag + kc);
            cp_async16(bDst0 + s * B_SS, Bg0 + kc);
            cp_async16(bDst1 + s * B_SS, Bg1 + kc);
            CP_COMMIT();
            CP_WAIT(1);
        } else {
            CP_WAIT(0);
        }
        __syncthreads();

        uint32_t sa = (c & 1) * A_SS, sb = (c & 1) * B_SS;
        #pragma unroll
        for (int ks = 0; ks < 2; ks++) {
            uint32_t af[2][4], bf[4][2];
            #pragma unroll
            for (int mt = 0; mt < 2; mt++)
                ldm_x4(af[mt], aAddr[mt] + sa + ks * 32);
            #pragma unroll
            for (int nt = 0; nt < 4; nt++)
                ldm_x2(bf[nt], bAddr[nt] + sb + ks * 32);
            #pragma unroll
            for (int mt = 0; mt < 2; mt++)
                #pragma unroll
                for (int nt = 0; nt < 4; nt++)
                    mma_bf16(acc[mt][nt], af[mt], bf[nt]);
        }
        __syncthreads();
    }

    int trow = lane >> 2, tcol = (lane & 3) * 2;
    float vals[2][4][2][2];
    #pragma unroll
    for (int mt = 0; mt < 2; mt++) {
        #pragma unroll
        for (int nt = 0; nt < 4; nt++) {
            int col = warp_n * 32 + nt * 8 + tcol;
            float b0 = bias[col], b1 = bias[col + 1];
            #pragma unroll
            for (int hh = 0; hh < 2; hh++) {
                int row = m0 + warp_m * 32 + mt * 16 + trow + hh * 8;
                float2 rv = *reinterpret_cast<const float2*>(&res[(long)row * N + col]);
                vals[mt][nt][hh][0] = acc[mt][nt][hh * 2 + 0] + b0 + rv.x;
                vals[mt][nt][hh][1] = acc[mt][nt][hh * 2 + 1] + b1 + rv.y;
            }
        }
    }
    #pragma unroll
    for (int mt = 0; mt < 2; mt++) {
        #pragma unroll
        for (int hh = 0; hh < 2; hh++) {
            float s = 0.0f, sq = 0.0f;
            #pragma unroll
            for (int nt = 0; nt < 4; nt++) {
                float a = vals[mt][nt][hh][0], bb = vals[mt][nt][hh][1];
                s += a + bb;
                sq += a * a + bb * bb;
            }
            s  += __shfl_xor_sync(0xffffffffu, s, 1);
            s  += __shfl_xor_sync(0xffffffffu, s, 2);
            sq += __shfl_xor_sync(0xffffffffu, sq, 1);
            sq += __shfl_xor_sync(0xffffffffu, sq, 2);
            if ((lane & 3) == 0) {
                int lr = warp_m * 32 + mt * 16 + trow + hh * 8;
                rsum[warp_n][lr] = s;
                rsq[warp_n][lr] = sq;
            }
        }
    }
    __syncthreads();
    if (tid < 64) {
        float su = rsum[0][tid] + rsum[1][tid] + rsum[2][tid] + rsum[3][tid];
        float sq = rsq[0][tid] + rsq[1][tid] + rsq[2][tid] + rsq[3][tid];
        float mean = su * (1.0f / 128.0f);
        float var = sq * (1.0f / 128.0f) - mean * mean;
        smean[tid] = mean;
        srstd[tid] = rsqrtf(var + 1e-5f);
    }
    __syncthreads();

    #pragma unroll
    for (int mt = 0; mt < 2; mt++) {
        #pragma unroll
        for (int nt = 0; nt < 4; nt++) {
            int col = warp_n * 32 + nt * 8 + tcol;
            float gg0 = g2[col], gg1 = g2[col + 1];
            float bb0 = b2[col], bb1 = b2[col + 1];
            #pragma unroll
            for (int hh = 0; hh < 2; hh++) {
                int lr = warp_m * 32 + mt * 16 + trow + hh * 8;
                int row = m0 + lr;
                float v0 = vals[mt][nt][hh][0], v1 = vals[mt][nt][hh][1];
                float2 hv = {v0, v1};
                *reinterpret_cast<float2*>(&H[(long)row * N + col]) = hv;
                float m = smean[lr], r = srstd[lr];
                float y0 = (v0 - m) * r * gg0 + bb0;
                float y1 = (v1 - m) * r * gg1 + bb1;
                __nv_bfloat162 p = __float22bfloat162_rn(make_float2(y0, y1));
                *reinterpret_cast<uint32_t*>(Y + (long)row * N + col) =
                    *reinterpret_cast<uint32_t*>(&p);
            }
        }
    }
}

// ---------------------------------------------------------------------------
// LayerNorm (LN1) -> bf16 out
// ---------------------------------------------------------------------------
__global__ void ln_kernel(const float* __restrict__ x,
                          const float* __restrict__ gamma,
                          const float* __restrict__ beta,
                          __nv_bfloat16* __restrict__ out) {
    int row = blockIdx.x;
    int t = threadIdx.x;
    float v = x[row * CDIM + t];

    __shared__ float s1[4], s2[4];
    int lane = t & 31, warp = t >> 5;

    float ws = v;
    #pragma unroll
    for (int off = 16; off; off >>= 1) ws += __shfl_xor_sync(0xffffffffu, ws, off);
    if (lane == 0) s1[warp] = ws;
    __syncthreads();
    float mean = (s1[0] + s1[1] + s1[2] + s1[3]) * (1.0f / CDIM);

    float d = v - mean;
    float ws2 = d * d;
    #pragma unroll
    for (int off = 16; off; off >>= 1) ws2 += __shfl_xor_sync(0xffffffffu, ws2, off);
    if (lane == 0) s2[warp] = ws2;
    __syncthreads();
    float var = (s2[0] + s2[1] + s2[2] + s2[3]) * (1.0f / CDIM);

    out[row * CDIM + t] =
        __float2bfloat16(d * rsqrtf(var + 1e-5f) * gamma[t] + beta[t]);
}

// ---------------------------------------------------------------------------
// Fully fused neighborhood attention (R11 config). Block = (by, h).
// 256 threads (8 warps).
// ---------------------------------------------------------------------------
__global__ void natt_kernel(const __nv_bfloat16* __restrict__ qkv,
                            const float* __restrict__ rpb,
                            __nv_bfloat16* __restrict__ out) {
    __shared__ uint32_t Vs[NBK * 64 * 16];      // 28672 B
    __shared__ float s_sc[NBK * 64];            // 1792 B
    __shared__ float rpb_s[169];                // 676 B
    __shared__ float wbuf[8][8][49];            // 12544 B
    __shared__ float qpart[8][HD];              // 1024 B
    __shared__ float qs[HD];                    // 128 B

    int blk = blockIdx.x;
    int by = blk >> 2, h = blk & 3;
    int b = by >> 6, y = by & 63;
    int sy = min(max(y - 3, 0), IMH - NBK);
    int tid = threadIdx.x;
    int wid = tid >> 5, lane = tid & 31;

    // --- qsum partial
    {
        int x = tid >> 2, dg = tid & 3;
        uint4 u = *reinterpret_cast<const uint4*>(
            &qkv[((long)(by * 64 + x)) * 384 + h * HD + dg * 8]);
        float2 f0 = bf2f(u.x), f1 = bf2f(u.y), f2 = bf2f(u.z), f3 = bf2f(u.w);
        float v[8] = {f0.x, f0.y, f1.x, f1.y, f2.x, f2.y, f3.x, f3.y};
        #pragma unroll
        for (int i = 0; i < 8; i++) {
            v[i] += __shfl_xor_sync(0xffffffffu, v[i], 4);
            v[i] += __shfl_xor_sync(0xffffffffu, v[i], 8);
            v[i] += __shfl_xor_sync(0xffffffffu, v[i], 16);
        }
        if (lane < 4) {
            #pragma unroll
            for (int i = 0; i < 8; i++)
                qpart[wid][lane * 8 + i] = v[i];
        }
    }

    // --- Stage V
    for (int i = tid; i < NBK * 64 * 4; i += 256) {
        int ky = i >> 8;
        int rem = i & 255;
        int col = rem >> 2, d8 = rem & 3;
        int np = (b * 64 + sy + ky) * 64 + col;
        uint4 u = *reinterpret_cast<const uint4*>(
            &qkv[(long)np * 384 + 2 * CDIM + h * HD + d8 * 8]);
        *reinterpret_cast<uint4*>(&Vs[((ky * 64 + col) << 4) + d8 * 4]) = u;
    }
    if (tid < 169) rpb_s[tid] = rpb[h * 169 + tid];
    __syncthreads();

    if (tid < HD) {
        float s = 0.0f;
        #pragma unroll
        for (int w = 0; w < 8; w++) s += qpart[w][tid];
        qs[tid] = s * 0.17677669529663687f;
    }
    __syncthreads();

    // --- Score dots: 448 dots, <=2 per thread
    #pragma unroll
    for (int rep = 0; rep < 2; rep++) {
        int d = rep * 256 + tid;
        if (d < NBK * 64) {
            int ky = d >> 6, nx = d & 63;
            const __nv_bfloat16* kb =
                qkv + ((long)((b * 64 + sy + ky) * 64 + nx)) * 384 + CDIM + h * HD;
            float acc = 0.0f;
            #pragma unroll
            for (int j = 0; j < 4; j++) {
                uint4 u = *reinterpret_cast<const uint4*>(kb + j * 8);
                float2 f0 = bf2f(u.x), f1 = bf2f(u.y), f2 = bf2f(u.z), f3 = bf2f(u.w);
                acc += f0.x * qs[j * 8 + 0] + f0.y * qs[j * 8 + 1]
                     + f1.x * qs[j * 8 + 2] + f1.y * qs[j * 8 + 3]
                     + f2.x * qs[j * 8 + 4] + f2.y * qs[j * 8 + 5]
                     + f3.x * qs[j * 8 + 6] + f3.y * qs[j * 8 + 7];
            }
            s_sc[d] = acc;
        }
    }
    __syncthreads();

    // --- Phase A: softmax weights for this warp's 8 pixels
    #pragma unroll 2
    for (int i = 0; i < 8; i++) {
        int x = wid * 8 + i;
        int sx = min(max(x - 3, 0), IMW - NBK);
        int ryo = (sy - y + 6) * 13 + (sx - x + 6);

        float s0, s1 = -1e30f;
        {
            int ky = lane / NBK, kx = lane - ky * NBK;
            s0 = s_sc[ky * 64 + sx + kx] + rpb_s[ryo + ky * 13 + kx];
        }
        if (lane < 17) {
            int n = lane + 32;
            int ky = n / NBK, kx = n - ky * NBK;
            s1 = s_sc[ky * 64 + sx + kx] + rpb_s[ryo + ky * 13 + kx];
        }
        float m = fmaxf(s0, s1);
        #pragma unroll
        for (int off = 16; off; off >>= 1)
            m = fmaxf(m, __shfl_xor_sync(0xffffffffu, m, off));
        float e0 = __expf(s0 - m);
        float e1 = (lane < 17) ? __expf(s1 - m) : 0.0f;
        float sum = e0 + e1;
        #pragma unroll
        for (int off = 16; off; off >>= 1)
            sum += __shfl_xor_sync(0xffffffffu, sum, off);
        float inv = 1.0f / sum;
        wbuf[wid][i][lane] = e0 * inv;
        if (lane < 17) wbuf[wid][i][lane + 32] = e1 * inv;
    }
    __syncwarp();

    // --- Phase B: lane = (g = lane>>2 pixel, qi = lane&3 quarter of channels)
    int g = lane >> 2, qi = lane & 3;
    int x = wid * 8 + g;
    int sx = min(max(x - 3, 0), IMW - NBK);
    const float* wp = wbuf[wid][g];

    float a0 = 0.f, a1 = 0.f, a2 = 0.f, a3 = 0.f,
          a4 = 0.f, a5 = 0.f, a6 = 0.f, a7 = 0.f;
    #pragma unroll
    for (int n = 0; n < 49; n++) {
        int ky = n / NBK, kx = n - ky * NBK;
        float wv = wp[n];
        uint4 u = *reinterpret_cast<const uint4*>(
            &Vs[((ky * 64 + sx + kx) << 4) + qi * 4]);
        float2 f0 = bf2f(u.x), f1 = bf2f(u.y), f2 = bf2f(u.z), f3 = bf2f(u.w);
        a0 = fmaf(wv, f0.x, a0); a1 = fmaf(wv, f0.y, a1);
        a2 = fmaf(wv, f1.x, a2); a3 = fmaf(wv, f1.y, a3);
        a4 = fmaf(wv, f2.x, a4); a5 = fmaf(wv, f2.y, a5);
        a6 = fmaf(wv, f3.x, a6); a7 = fmaf(wv, f3.y, a7);
    }
    int p = (b * 64 + y) * 64 + x;
    __nv_bfloat162 p0 = __float22bfloat162_rn(make_float2(a0, a1));
    __nv_bfloat162 p1 = __float22bfloat162_rn(make_float2(a2, a3));
    __nv_bfloat162 p2 = __float22bfloat162_rn(make_float2(a4, a5));
    __nv_bfloat162 p3 = __float22bfloat162_rn(make_float2(a6, a7));
    uint4 ov;
    ov.x = *reinterpret_cast<uint32_t*>(&p0);
    ov.y = *reinterpret_cast<uint32_t*>(&p1);
    ov.z = *reinterpret_cast<uint32_t*>(&p2);
    ov.w = *reinterpret_cast<uint32_t*>(&p3);
    *reinterpret_cast<uint4*>(out + (long)p * CDIM + h * HD + qi * 8) = ov;
}

// ---------------------------------------------------------------------------
extern "C" void kernel_launch(void* const* d_in, const int* in_sizes, int n_in,
                              void* d_out, int out_size) {
    const float* x      = (const float*)d_in[0];
    const float* ln1_g  = (const float*)d_in[1];
    const float* ln1_b  = (const float*)d_in[2];
    const float* qkv_w  = (const float*)d_in[3];
    const float* qkv_b  = (const float*)d_in[4];
    const float* rpb    = (const float*)d_in[5];
    const float* proj_w = (const float*)d_in[6];
    const float* proj_b = (const float*)d_in[7];
    const float* ln2_g  = (const float*)d_in[8];
    const float* ln2_b  = (const float*)d_in[9];
    const float* fc1_w  = (const float*)d_in[10];
    const float* fc1_b  = (const float*)d_in[11];
    const float* fc2_w  = (const float*)d_in[12];
    const float* fc2_b  = (const float*)d_in[13];
    float* out = (float*)d_out;

    __nv_bfloat16 *xn, *qkvb, *attnb, *yb, *mlpb;
    float *hb;
    cudaGetSymbolAddress((void**)&xn,    g_xn);
    cudaGetSymbolAddress((void**)&qkvb,  g_qkv);
    cudaGetSymbolAddress((void**)&attnb, g_attn);
    cudaGetSymbolAddress((void**)&hb,    g_h);
    cudaGetSymbolAddress((void**)&yb,    g_y);
    cudaGetSymbolAddress((void**)&mlpb,  g_mlp);
    __nv_bfloat16 *wqkvT, *wprojT, *wfc1T, *wfc2T;
    cudaGetSymbolAddress((void**)&wqkvT, g_wqkvT);
    cudaGetSymbolAddress((void**)&wprojT, g_wprojT);
    cudaGetSymbolAddress((void**)&wfc1T, g_wfc1T);
    cudaGetSymbolAddress((void**)&wfc2T, g_wfc2T);

    // 0. Weight prep
    prep_w_kernel<<<768, 256>>>(qkv_w, proj_w, fc1_w, fc2_w);
    // 1. LN1 -> bf16
    ln_kernel<<<NPIX, CDIM>>>(x, ln1_g, ln1_b, xn);
    // 2. QKV GEMM -> bf16 qkv
    mma_gemm_kernel<<<dim3(3, 256), 256>>>(xn, wqkvT, qkv_b, nullptr,
                                           qkvb, 384, 128, 0, 1);
    // 3. Fused neighborhood attention
    natt_kernel<<<BATCH * IMH * NHEADS, 256>>>(qkvb, rpb, attnb);
    // 4. Proj GEMM + residual(x) + LN2 -> h (fp32) & y (bf16)
    proj_ln_kernel<<<dim3(1, 256), 256>>>(attnb, wprojT, proj_b, x,
                                          ln2_g, ln2_b, hb, yb);
    // 5. FC1 GEMM + GELU (bf16 out)
    mma_gemm_kernel<<<dim3(4, 256), 256>>>(yb, wfc1T, fc1_b, nullptr,
                                           mlpb, 512, 128, 2, 1);
    // 6. FC2 GEMM + residual(h) -> out (fp32)
    mma_gemm_kernel<<<dim3(1, 256), 256>>>(mlpb, wfc2T, fc2_b, hb,
                                           out, 128, 512, 1, 0);
}